// round 17
// baseline (speedup 1.0000x reference)
#include <cuda_runtime.h>
#include <cuda_fp16.h>
#include <cstdint>

#define T_DIM 4096
#define NUM_TILES 2048
#define THREADS 256

// ---- shared memory layout (bytes) ----
// VF: v_tp fp16 fragment-packed: [ksg(16)][J(8)][lane(32)][16B = nb-even 8B | nb-odd 8B]
#define VF_OFF 0
// A rings: per group: 3 stages x 4KB fp16 fragment-major chunks:
//   stage = [ks(2)][mtblock(4)][lane(32)][16B fragment cell]
#define A_OFF  65536
#define STAGE_BYTES 4096
#define GROUP_RING 12288
#define W_OFF  90112
#define SC_OFF 90624       // 128 floats: [group(2)][row(64)]
#define SMEM_BYTES 91136

__device__ __forceinline__ uint32_t pack2h(float lo, float hi) {
    uint32_t r;
    asm("cvt.rn.f16x2.f32 %0, %1, %2;" : "=r"(r) : "f"(hi), "f"(lo));
    return r;
}

__device__ __forceinline__ float tanh_fast(float x) {
    float r;
    asm("tanh.approx.f32 %0, %1;" : "=f"(r) : "f"(x));
    return r;
}

__device__ __forceinline__ void sts64(uint32_t addr, uint32_t a, uint32_t b) {
    asm volatile("st.shared.v2.b32 [%0], {%1,%2};" :: "r"(addr), "r"(a), "r"(b) : "memory");
}

__device__ __forceinline__ void sts128(uint32_t addr, uint32_t a, uint32_t b, uint32_t c, uint32_t d) {
    asm volatile("st.shared.v4.b32 [%0], {%1,%2,%3,%4};"
                 :: "r"(addr), "r"(a), "r"(b), "r"(c), "r"(d) : "memory");
}

__device__ __forceinline__ void lds128(uint32_t* r, uint32_t addr) {
    asm volatile("ld.shared.v4.b32 {%0,%1,%2,%3}, [%4];"
                 : "=r"(r[0]), "=r"(r[1]), "=r"(r[2]), "=r"(r[3]) : "r"(addr));
}

__device__ __forceinline__ void mma16(float* c, const uint32_t* a, uint32_t b0, uint32_t b1) {
    asm volatile(
        "mma.sync.aligned.m16n8k16.row.col.f32.f16.f16.f32 "
        "{%0,%1,%2,%3}, {%4,%5,%6,%7}, {%8,%9}, {%0,%1,%2,%3};\n"
        : "+f"(c[0]), "+f"(c[1]), "+f"(c[2]), "+f"(c[3])
        : "r"(a[0]), "r"(a[1]), "r"(a[2]), "r"(a[3]), "r"(b0), "r"(b1));
}

__device__ __forceinline__ void bar_grp(int group) {
    asm volatile("bar.sync %0, 128;" :: "r"(group + 1) : "memory");
}

// LDG this thread's 2 fragment cells (ks=0,1) for chunk gc: 4 float4.
// Cell (ks, mt, lane=g*4+t): rows mt*16+g and +8, phys k = ck*32 + ks*16 + 4t.
__device__ __forceinline__ void ldg_cells(float4* rg, int gc, int gtid, int group,
                                          const float* h1, const float* h2,
                                          int bx, int grid) {
    int tile = bx + (gc >> 3) * grid;
    int ck = gc & 7;
    int mt = (gtid >> 5) & 3;
    int lane = gtid & 31;
    int g = lane >> 2, t = lane & 3;
    int r_lo = mt * 16 + g;
    const float* hp = (g & 1) ? h2 : h1;
    const float4* base = (const float4*)hp
        + (size_t)(tile * 64 + group * 32 + (r_lo >> 1)) * 64 + ck * 8 + t;
    rg[0] = __ldg(base);             // ks0, row lo
    rg[1] = __ldg(base + 4 * 64);    // ks0, row lo+8 (pair +4)
    rg[2] = __ldg(base + 4);         // ks1, row lo
    rg[3] = __ldg(base + 4 + 4 * 64);
}

// convert + store both cells into stage (gc%3), fragment-major
__device__ __forceinline__ void sts_cells(const float4* rg, int gc, int gtid, int group,
                                          uint32_t smem_u32) {
    uint32_t base = smem_u32 + A_OFF +
        (uint32_t)(group * GROUP_RING + (gc % 3) * STAGE_BYTES);
    int mt = (gtid >> 5) & 3;
    int lane = gtid & 31;
    uint32_t a0 = base + (uint32_t)(mt * 512 + lane * 16);
    sts128(a0,
           pack2h(rg[0].x, rg[0].y), pack2h(rg[1].x, rg[1].y),
           pack2h(rg[0].z, rg[0].w), pack2h(rg[1].z, rg[1].w));
    sts128(a0 + 2048,
           pack2h(rg[2].x, rg[2].y), pack2h(rg[3].x, rg[3].y),
           pack2h(rg[2].z, rg[2].w), pack2h(rg[3].z, rg[3].w));
}

__global__ void __launch_bounds__(THREADS, 2)
topo_attention_v9(const float* __restrict__ h1,
                  const float* __restrict__ h2,
                  const float* __restrict__ w,
                  const float* __restrict__ v,
                  float* __restrict__ out) {
    extern __shared__ char smem[];
    uint32_t smem_u32;
    asm("{ .reg .u64 t; cvta.to.shared.u64 t, %1; cvt.u32.u64 %0, t; }"
        : "=r"(smem_u32) : "l"(smem));
    float* w_s  = (float*)(smem + W_OFF);
    float* sc_s = (float*)(smem + SC_OFF);

    const int tid  = threadIdx.x;
    const int bx = blockIdx.x;
    const int grid = gridDim.x;

    // ---- prologue: VF pack (fp16, K-permuted fragment layout), w, sc ----
    for (int i = tid * 4; i < 32768; i += THREADS * 4) {
        float4 vv = *(const float4*)(v + i);
        int l = i >> 8, m = i & 255;
        int ksg = m >> 4, tp = (m >> 2) & 3;
        int nb = l >> 3, gp = l & 7;
        uint32_t addr = smem_u32 + VF_OFF +
            (uint32_t)(ksg * 4096 + (nb >> 1) * 512 + (gp * 4 + tp) * 16 + (nb & 1) * 8);
        sts64(addr, pack2h(vv.x, vv.y), pack2h(vv.z, vv.w));
    }
    if (tid < 128) { w_s[tid] = w[tid]; sc_s[tid] = 0.0f; }
    __syncthreads();

    int ntile = 0;
    for (int t = bx; t < NUM_TILES; t += grid) ntile++;
    const int NCH = ntile * 8;   // K=32 chunks

    // ---- group decomposition: 2 independent 4-warp pipelines ----
    const int group = tid >> 7;       // 0,1
    const int gtid  = tid & 127;
    const int gwid  = gtid >> 5;      // 0..3 within group
    const int lane  = tid & 31;
    const int warp_m = gwid >> 1;     // 2 m-groups of 32 rows
    const int warp_n = gwid & 1;      // 2 n-groups of 64
    const int g   = lane >> 2;
    const int tig = lane & 3;

    const uint32_t vb = smem_u32 + VF_OFF + (uint32_t)(warp_n * 2048 + lane * 16);
    const uint32_t ring_base = smem_u32 + A_OFF + (uint32_t)(group * GROUP_RING);
    const uint32_t afr_off = (uint32_t)(warp_m * 1024 + lane * 16);  // + mti*512 + ks*2048

    float acc[2][8][4];
    #pragma unroll
    for (int mt = 0; mt < 2; mt++)
        #pragma unroll
        for (int nt = 0; nt < 8; nt++)
            #pragma unroll
            for (int i = 0; i < 4; i++) acc[mt][nt][i] = 0.0f;

    float4 rg[4];
    ldg_cells(rg, 0, gtid, group, h1, h2, bx, grid);
    sts_cells(rg, 0, gtid, group, smem_u32);
    if (NCH > 1) ldg_cells(rg, 1, gtid, group, h1, h2, bx, grid);

    for (int gc = 0; gc < NCH; ++gc) {
        bar_grp(group);   // STS(gc) visible group-wide AND group done with MMA(gc-1)

        if (gc + 1 < NCH) sts_cells(rg, gc + 1, gtid, group, smem_u32);
        if (gc + 2 < NCH) ldg_cells(rg, gc + 2, gtid, group, h1, h2, bx, grid);

        uint32_t ab = ring_base + (uint32_t)((gc % 3) * STAGE_BYTES) + afr_off;
        #pragma unroll
        for (int ks = 0; ks < 2; ++ks) {
            int ksg = (gc & 7) * 2 + ks;
            uint32_t bb[4][4];
            #pragma unroll
            for (int jj = 0; jj < 4; ++jj)
                lds128(bb[jj], vb + (uint32_t)(ksg * 4096 + jj * 512));

            uint32_t afr[2][4];
            lds128(afr[0], ab + (uint32_t)(ks * 2048));
            lds128(afr[1], ab + (uint32_t)(ks * 2048 + 512));

            #pragma unroll
            for (int mt = 0; mt < 2; ++mt)
                #pragma unroll
                for (int jj = 0; jj < 4; ++jj) {
                    mma16(acc[mt][2 * jj],     afr[mt], bb[jj][0], bb[jj][1]);
                    mma16(acc[mt][2 * jj + 1], afr[mt], bb[jj][2], bb[jj][3]);
                }
        }

        if ((gc & 7) == 7) {
            // ---- group-local epilogue for tile = bx + (gc>>3)*grid ----
            int tile = bx + (gc >> 3) * grid;
            float part[4];
            #pragma unroll
            for (int mt = 0; mt < 2; ++mt) {
                float p0 = 0.f, p1 = 0.f;
                #pragma unroll
                for (int nt = 0; nt < 8; ++nt) {
                    int l0 = warp_n * 64 + nt * 8 + tig * 2;
                    float w0 = w_s[l0], w1 = w_s[l0 + 1];
                    p0 += w0 * tanh_fast(acc[mt][nt][0]) + w1 * tanh_fast(acc[mt][nt][1]);
                    p1 += w0 * tanh_fast(acc[mt][nt][2]) + w1 * tanh_fast(acc[mt][nt][3]);
                    #pragma unroll
                    for (int i = 0; i < 4; i++) acc[mt][nt][i] = 0.0f;
                }
                part[mt * 2] = p0;
                part[mt * 2 + 1] = p1;
            }
            #pragma unroll
            for (int i = 0; i < 4; i++) {
                part[i] += __shfl_xor_sync(0xffffffffu, part[i], 1);
                part[i] += __shfl_xor_sync(0xffffffffu, part[i], 2);
            }
            if (tig == 0) {
                #pragma unroll
                for (int i = 0; i < 4; i++) {
                    int row = warp_m * 32 + (i >> 1) * 16 + (i & 1) * 8 + g;  // local 0..63
                    atomicAdd(&sc_s[group * 64 + row], part[i]);
                }
            }
            bar_grp(group);   // group's atomicAdds visible
            if (gtid < 32) {
                float s0 = sc_s[group * 64 + 2 * gtid];
                float s1 = sc_s[group * 64 + 2 * gtid + 1];
                sc_s[group * 64 + 2 * gtid] = 0.0f;
                sc_s[group * 64 + 2 * gtid + 1] = 0.0f;
                int P = tile * 64 + group * 32 + gtid;    // global (b*T + t)
                int b = P >> 12;
                int t = P & 4095;
                float a0 = 1.0f / (1.0f + __expf(s1 - s0));
                out[((b * 2) + 0) * T_DIM + t] = a0;
                out[((b * 2) + 1) * T_DIM + t] = 1.0f - a0;
            }
            bar_grp(group);   // re-zero visible before next tile's atomics
        }
    }
}

extern "C" void kernel_launch(void* const* d_in, const int* in_sizes, int n_in,
                              void* d_out, int out_size) {
    const float* h1 = (const float*)d_in[0];
    const float* h2 = (const float*)d_in[1];
    const float* w  = (const float*)d_in[2];
    const float* v  = (const float*)d_in[3];
    float* out = (float*)d_out;

    cudaFuncSetAttribute(topo_attention_v9,
                         cudaFuncAttributeMaxDynamicSharedMemorySize, SMEM_BYTES);

    int nsm = 148;
    if (cudaDeviceGetAttribute(&nsm, cudaDevAttrMultiProcessorCount, 0) != cudaSuccess || nsm <= 0)
        nsm = 148;

    topo_attention_v9<<<2 * nsm, THREADS, SMEM_BYTES>>>(h1, h2, w, v, out);
}